// round 6
// baseline (speedup 1.0000x reference)
#include <cuda_runtime.h>

// Problem constants
#define NB     8
#define NP     2048
#define BN     (NB * NP)
#define ITERS  50
#define PHASES (2 * ITERS)
#define NWARP  8
#define JCH    (NP / NWARP)      // 256 j's per warp
#define GRID   256               // 32 blocks per batch, 64 rows per block
#define BPB    32                // blocks per batch
#define TPB    256

// eps = 0.005
#define SF      288.5390081777927f    // 1/(eps*ln2)
#define TWOSF   577.0780163555854f    // 2/(eps*ln2)
#define EPSLN2  0.0034657359027997264f
#define LOG2NF  11.0f

// pk = (x, y, z, h) with h = s*(pot - |p|^2); coords immutable, .w mutated.
__device__ float4   g_pk1[BN], g_pk2[BN];
__device__ float    g_sq1[BN], g_sq2[BN];
__device__ float    g_part[GRID];
__device__ unsigned g_barr[NB * 32];   // per-batch arrive counters (128B apart)
__device__ unsigned g_brel[NB * 32];   // per-batch release epochs
__device__ unsigned g_fin;             // final arrive counter

// ---------------- helpers ----------------
__device__ __forceinline__ float ex2f(float x) {
    float r; asm("ex2.approx.ftz.f32 %0, %1;" : "=f"(r) : "f"(x)); return r;
}
__device__ __forceinline__ float lg2f(float x) {
    float r; asm("lg2.approx.ftz.f32 %0, %1;" : "=f"(r) : "f"(x)); return r;
}
__device__ __forceinline__ unsigned ld_acq(const unsigned* p) {
    unsigned v; asm volatile("ld.acquire.gpu.global.u32 %0, [%1];" : "=r"(v) : "l"(p) : "memory"); return v;
}
__device__ __forceinline__ unsigned atom_add_rel(unsigned* p, unsigned v) {
    unsigned o; asm volatile("atom.release.gpu.global.add.u32 %0, [%1], %2;" : "=r"(o) : "l"(p), "r"(v) : "memory"); return o;
}
__device__ __forceinline__ void st_rel(unsigned* p, unsigned v) {
    asm volatile("st.release.gpu.global.u32 [%0], %1;" :: "l"(p), "r"(v) : "memory");
}
__device__ __forceinline__ float4 ldcg4(const float4* p) {
    float4 r; asm volatile("ld.global.cg.v4.f32 {%0,%1,%2,%3}, [%4];"
        : "=f"(r.x), "=f"(r.y), "=f"(r.z), "=f"(r.w) : "l"(p)); return r;
}
__device__ __forceinline__ float ldcgf(const float* p) {
    float r; asm volatile("ld.global.cg.f32 %0, [%1];" : "=f"(r) : "l"(p)); return r;
}
__device__ __forceinline__ void stcgf(float* p, float v) {
    asm volatile("st.global.cg.f32 [%0], %1;" :: "l"(p), "f"(v));
}

// Per-batch grid barrier (BPB blocks). epoch counts from 1, monotonic counter.
__device__ __forceinline__ void batch_barrier(int b, unsigned epoch) {
    __threadfence();
    __syncthreads();
    if (threadIdx.x == 0) {
        unsigned* cnt = &g_barr[b * 32];
        unsigned* rel = &g_brel[b * 32];
        unsigned old = atom_add_rel(cnt, 1u);
        if (old == epoch * (unsigned)BPB - 1u) st_rel(rel, epoch);
        else while (ld_acq(rel) < epoch) __nanosleep(32);
    }
    __syncthreads();
}

// ---------------------------------------------------------------------------
// Single persistent kernel: init + 100 Sinkhorn half-steps + dist + reduce.
// 256 blocks = 8 batches x 32 blocks; each block owns 64 rows (2 groups of
// 32, processed sequentially against one staged j-tile). 8 warps/block:
// lane = row-in-group, warp w = j-chunk of 256.
// ---------------------------------------------------------------------------
__global__ void __launch_bounds__(TPB, 4) emd_k(
    const float* __restrict__ pc1, const float* __restrict__ pc2,
    float* __restrict__ out)
{
    __shared__ __align__(16) float4 sj[NP];        // 32 KB j-side tile
    __shared__ float ssq[NP];                      // |q|^2 (dist phase)
    __shared__ float msh[NWARP][32], ssh[NWARP][32];
    __shared__ float red[TPB];

    const int tid  = threadIdx.x;
    const int lane = tid & 31;
    const int w    = tid >> 5;
    const int blk  = blockIdx.x;
    const int b    = blk >> 5;                     // batch (32 blocks each)
    const int base = b * NP;
    const int row0 = base + ((blk & (BPB - 1)) << 6);   // first of 64 rows

    // ---- init: this block's 64 rows, both sets ----
    if (tid < 64) {
        int p = row0 + tid;
        float x = pc1[3 * p], y = pc1[3 * p + 1], z = pc1[3 * p + 2];
        float sq = x * x + y * y + z * z;
        g_pk1[p] = make_float4(x, y, z, -SF * sq);
        g_sq1[p] = sq;
        x = pc2[3 * p]; y = pc2[3 * p + 1]; z = pc2[3 * p + 2];
        sq = x * x + y * y + z * z;
        g_pk2[p] = make_float4(x, y, z, -SF * sq);
        g_sq2[p] = sq;
    }
    batch_barrier(b, 1);

    // ---- Sinkhorn half-steps ----
    #pragma unroll 1
    for (int p = 0; p < PHASES; p++) {
        const float4* jin = (p & 1) ? g_pk1 : g_pk2;   // j-side (fresh h)
        float4*       io  = (p & 1) ? g_pk2 : g_pk1;   // i-side / output h

        // stage j-side (coords + fresh h) through L2
        #pragma unroll
        for (int t = 0; t < NP / TPB; t++)
            sj[t * TPB + tid] = ldcg4(jin + base + t * TPB + tid);
        __syncthreads();

        #pragma unroll 1
        for (int g = 0; g < 2; g++) {
            const int gi = row0 + (g << 5) + lane;
            float4 pp = ldcg4(io + gi);
            float px = TWOSF * pp.x, py = TWOSF * pp.y, pz = TWOSF * pp.z;

            const float4* q = sj + w * JCH;
            float4 q0 = q[0];
            float m  = fmaf(px, q0.x, fmaf(py, q0.y, fmaf(pz, q0.z, q0.w)));
            float s0 = 0.f, s1 = 0.f, s2 = 0.f, s3 = 0.f;

            #pragma unroll 1
            for (int j = 0; j < JCH; j += 8) {
                float A[8];
                #pragma unroll
                for (int k = 0; k < 8; k++) {
                    float4 qq = q[j + k];
                    A[k] = fmaf(px, qq.x, fmaf(py, qq.y, fmaf(pz, qq.z, qq.w)));
                }
                float c = fmaxf(fmaxf(fmaxf(A[0], A[1]), fmaxf(A[2], A[3])),
                                fmaxf(fmaxf(A[4], A[5]), fmaxf(A[6], A[7])));
                float d  = fmaxf(c - m, 0.0f);     // branchless rescale
                float sc = ex2f(-d);
                m += d;
                s0 = fmaf(s0, sc, ex2f(A[0] - m));
                s1 = fmaf(s1, sc, ex2f(A[1] - m));
                s2 = fmaf(s2, sc, ex2f(A[2] - m));
                s3 = fmaf(s3, sc, ex2f(A[3] - m));
                s0 += ex2f(A[4] - m);
                s1 += ex2f(A[5] - m);
                s2 += ex2f(A[6] - m);
                s3 += ex2f(A[7] - m);
            }

            msh[w][lane] = m;
            ssh[w][lane] = (s0 + s1) + (s2 + s3);
            __syncthreads();

            if (w == 0) {
                float M = msh[0][lane];
                #pragma unroll
                for (int k = 1; k < NWARP; k++) M = fmaxf(M, msh[k][lane]);
                float S = 0.f;
                #pragma unroll
                for (int k = 0; k < NWARP; k++) S += ssh[k][lane] * ex2f(msh[k][lane] - M);
                stcgf(((float*)(io + gi)) + 3, -LOG2NF - M - lg2f(S));
            }
            __syncthreads();
        }
        batch_barrier(b, (unsigned)(p + 2));
    }

    // ---- dist phase: rows = set1, j = set2 ----
    {
        #pragma unroll
        for (int t = 0; t < NP / TPB; t++) {
            int idx = t * TPB + tid;
            sj[idx]  = ldcg4(g_pk2 + base + idx);
            ssq[idx] = __ldg(g_sq2 + base + idx);
        }
        __syncthreads();

        float vblk = 0.f;
        #pragma unroll 1
        for (int g = 0; g < 2; g++) {
            const int gi = row0 + (g << 5) + lane;
            float4 pp = ldcg4(g_pk1 + gi);
            float px = TWOSF * pp.x, py = TWOSF * pp.y, pz = TWOSF * pp.z;
            float tf  = pp.w;
            float sq1 = __ldg(g_sq1 + gi);

            const float4* q  = sj  + w * JCH;
            const float*  r2 = ssq + w * JCH;

            float a0 = 0.f, a1 = 0.f, a2 = 0.f, a3 = 0.f;
            #pragma unroll 1
            for (int j = 0; j < JCH; j += 4) {
                #pragma unroll
                for (int k = 0; k < 4; k++) {
                    float4 qq = q[j + k];
                    float  A  = fmaf(px, qq.x, fmaf(py, qq.y, fmaf(pz, qq.z, qq.w)));
                    float  e  = ex2f(tf + A);
                    float  C  = sq1 + r2[j + k] - (A - qq.w) * EPSLN2;
                    float  pc = e * C;
                    if      (k == 0) a0 += pc;
                    else if (k == 1) a1 += pc;
                    else if (k == 2) a2 += pc;
                    else             a3 += pc;
                }
            }
            ssh[w][lane] = (a0 + a1) + (a2 + a3);
            __syncthreads();

            if (w == 0) {
                float S = ssh[0][lane];
                #pragma unroll
                for (int k = 1; k < NWARP; k++) S += ssh[k][lane];
                float v = sqrtf((float)NP * S + 1e-12f);
                #pragma unroll
                for (int o = 16; o; o >>= 1) v += __shfl_xor_sync(0xffffffffu, v, o);
                vblk += v;
            }
            __syncthreads();
        }
        if (w == 0 && lane == 0) stcgf(&g_part[blk], vblk);
    }

    // ---- final: all blocks arrive; block 0 reduces deterministically ----
    __threadfence();
    __syncthreads();
    if (tid == 0) atom_add_rel(&g_fin, 1u);
    if (blk != 0) return;

    if (tid == 0) { while (ld_acq(&g_fin) < (unsigned)GRID) __nanosleep(32); }
    __syncthreads();

    red[tid] = ldcgf(&g_part[tid]);
    __syncthreads();
    #pragma unroll
    for (int s = TPB / 2; s > 0; s >>= 1) {
        if (tid < s) red[tid] += red[tid + s];
        __syncthreads();
    }
    if (tid == 0) {
        out[0] = red[0] * (1.0f / (float)BN);
        // reset barrier state for the next graph replay
        g_fin = 0;
        #pragma unroll
        for (int k = 0; k < NB; k++) { g_barr[k * 32] = 0; g_brel[k * 32] = 0; }
    }
}

// ---------------------------------------------------------------------------
extern "C" void kernel_launch(void* const* d_in, const int* in_sizes, int n_in,
                              void* d_out, int out_size) {
    const float* pc1 = (const float*)d_in[0];
    const float* pc2 = (const float*)d_in[1];
    float* out = (float*)d_out;

    emd_k<<<GRID, TPB>>>(pc1, pc2, out);

    (void)in_sizes; (void)n_in; (void)out_size;
}

// round 7
// speedup vs baseline: 1.1817x; 1.1817x over previous
#include <cuda_runtime.h>

// Problem constants
#define NB    8
#define NP    2048
#define BN    (NB * NP)
#define ITERS 50
#define PHASES (2 * ITERS)
#define SAFEP 10                 // warmup phases with online-max (safe) kernel
#define NWARP 8                  // j-split warps per 32-row group
#define JCH   (NP / NWARP)       // 256 j's per warp
#define TPB   (32 * NWARP)

// eps = 0.005
#define SF      288.5390081777927f    // 1/(eps*ln2)
#define TWOSF   577.0780163555854f    // 2/(eps*ln2)
#define EPSLN2  0.0034657359027997264f
#define LOG2NF  11.0f

// pk = (x, y, z, h) with h = s*(pot - |p|^2); coords immutable, .w mutated.
__device__ float4 g_pk1[BN], g_pk2[BN];
__device__ float  g_sq1[BN], g_sq2[BN];
__device__ float  g_part[BN / 32];

__device__ __forceinline__ float ex2f(float x) {
    float r; asm("ex2.approx.ftz.f32 %0, %1;" : "=f"(r) : "f"(x)); return r;
}
__device__ __forceinline__ float lg2f(float x) {
    float r; asm("lg2.approx.ftz.f32 %0, %1;" : "=f"(r) : "f"(x)); return r;
}

// ---------------------------------------------------------------------------
__global__ void init_k(const float* __restrict__ pc1, const float* __restrict__ pc2) {
    int idx = blockIdx.x * blockDim.x + threadIdx.x;
    if (idx >= BN) return;

    float x = pc1[3 * idx + 0], y = pc1[3 * idx + 1], z = pc1[3 * idx + 2];
    float sq = x * x + y * y + z * z;
    g_pk1[idx] = make_float4(x, y, z, -SF * sq);
    g_sq1[idx] = sq;

    x = pc2[3 * idx + 0]; y = pc2[3 * idx + 1]; z = pc2[3 * idx + 2];
    sq = x * x + y * y + z * z;
    g_pk2[idx] = make_float4(x, y, z, -SF * sq);
    g_sq2[idx] = sq;
}

// ---------------------------------------------------------------------------
// SAFE half-step (warmup): online max, branchless rescale.
//   A_j = 2s p_i . q_j + h_j ; h_out_i = -log2N - LSE2_j(A_j)
// ---------------------------------------------------------------------------
__global__ void __launch_bounds__(TPB, 4) upd_safe_k(int dir) {
    const float4* __restrict__ jin = dir ? g_pk1 : g_pk2;
    float4*       __restrict__ io  = dir ? g_pk2 : g_pk1;

    __shared__ __align__(16) float4 sj[NP];
    __shared__ float msh[NWARP][32], ssh[NWARP][32];

    int lane = threadIdx.x & 31;
    int w    = threadIdx.x >> 5;
    int blk  = blockIdx.x;
    int b    = blk >> 6;
    int base = b * NP;
    int gi   = base + ((blk & 63) << 5) + lane;

    #pragma unroll
    for (int t = 0; t < NP / TPB; t++)
        sj[t * TPB + threadIdx.x] = __ldg(jin + base + t * TPB + threadIdx.x);

    float4 pp = __ldg(io + gi);
    float px = TWOSF * pp.x, py = TWOSF * pp.y, pz = TWOSF * pp.z;
    __syncthreads();

    const float4* q = sj + w * JCH;
    float4 q0 = q[0];
    float m  = fmaf(px, q0.x, fmaf(py, q0.y, fmaf(pz, q0.z, q0.w)));
    float s0 = 0.f, s1 = 0.f, s2 = 0.f, s3 = 0.f;

    #pragma unroll 1
    for (int j = 0; j < JCH; j += 8) {
        float A[8];
        #pragma unroll
        for (int k = 0; k < 8; k++) {
            float4 qq = q[j + k];
            A[k] = fmaf(px, qq.x, fmaf(py, qq.y, fmaf(pz, qq.z, qq.w)));
        }
        float c = fmaxf(fmaxf(fmaxf(A[0], A[1]), fmaxf(A[2], A[3])),
                        fmaxf(fmaxf(A[4], A[5]), fmaxf(A[6], A[7])));
        float d  = fmaxf(c - m, 0.0f);
        float sc = ex2f(-d);
        m += d;
        s0 = fmaf(s0, sc, ex2f(A[0] - m));
        s1 = fmaf(s1, sc, ex2f(A[1] - m));
        s2 = fmaf(s2, sc, ex2f(A[2] - m));
        s3 = fmaf(s3, sc, ex2f(A[3] - m));
        s0 += ex2f(A[4] - m);
        s1 += ex2f(A[5] - m);
        s2 += ex2f(A[6] - m);
        s3 += ex2f(A[7] - m);
    }

    msh[w][lane] = m;
    ssh[w][lane] = (s0 + s1) + (s2 + s3);
    __syncthreads();

    if (w == 0) {
        float M = msh[0][lane];
        #pragma unroll
        for (int k = 1; k < NWARP; k++) M = fmaxf(M, msh[k][lane]);
        float S = 0.f;
        #pragma unroll
        for (int k = 0; k < NWARP; k++) S += ssh[k][lane] * ex2f(msh[k][lane] - M);
        ((float*)(io + gi))[3] = -LOG2NF - M - lg2f(S);
    }
}

// ---------------------------------------------------------------------------
// FAST half-step: fixed per-row reference M0 = -h_old - log2N (= previous LSE).
//   x_j = A_j - M0 = 2s p.q_j + h_j + h_old + log2N
//   h_new = h_old - lg2( sum_j 2^x_j )            (exact for any reference)
// No max tracking, no serial spine, plain-sum merge. 7 warp-instrs per j.
// ---------------------------------------------------------------------------
__global__ void __launch_bounds__(TPB, 4) upd_fast_k(int dir) {
    const float4* __restrict__ jin = dir ? g_pk1 : g_pk2;
    float4*       __restrict__ io  = dir ? g_pk2 : g_pk1;

    __shared__ __align__(16) float4 sj[NP];
    __shared__ float ssh[NWARP][32];

    int lane = threadIdx.x & 31;
    int w    = threadIdx.x >> 5;
    int blk  = blockIdx.x;
    int b    = blk >> 6;
    int base = b * NP;
    int gi   = base + ((blk & 63) << 5) + lane;

    #pragma unroll
    for (int t = 0; t < NP / TPB; t++)
        sj[t * TPB + threadIdx.x] = __ldg(jin + base + t * TPB + threadIdx.x);

    float4 pp = __ldg(io + gi);
    float px = TWOSF * pp.x, py = TWOSF * pp.y, pz = TWOSF * pp.z;
    float hw = pp.w + LOG2NF;             // -M0
    __syncthreads();

    const float4* q = sj + w * JCH;
    float s0 = 0.f, s1 = 0.f, s2 = 0.f, s3 = 0.f;

    #pragma unroll 2
    for (int j = 0; j < JCH; j += 8) {
        float e0, e1, e2, e3, e4, e5, e6, e7;
        {
            float4 qq = q[j + 0];
            e0 = ex2f(fmaf(px, qq.x, fmaf(py, qq.y, fmaf(pz, qq.z, qq.w))) + hw);
        }
        {
            float4 qq = q[j + 1];
            e1 = ex2f(fmaf(px, qq.x, fmaf(py, qq.y, fmaf(pz, qq.z, qq.w))) + hw);
        }
        {
            float4 qq = q[j + 2];
            e2 = ex2f(fmaf(px, qq.x, fmaf(py, qq.y, fmaf(pz, qq.z, qq.w))) + hw);
        }
        {
            float4 qq = q[j + 3];
            e3 = ex2f(fmaf(px, qq.x, fmaf(py, qq.y, fmaf(pz, qq.z, qq.w))) + hw);
        }
        {
            float4 qq = q[j + 4];
            e4 = ex2f(fmaf(px, qq.x, fmaf(py, qq.y, fmaf(pz, qq.z, qq.w))) + hw);
        }
        {
            float4 qq = q[j + 5];
            e5 = ex2f(fmaf(px, qq.x, fmaf(py, qq.y, fmaf(pz, qq.z, qq.w))) + hw);
        }
        {
            float4 qq = q[j + 6];
            e6 = ex2f(fmaf(px, qq.x, fmaf(py, qq.y, fmaf(pz, qq.z, qq.w))) + hw);
        }
        {
            float4 qq = q[j + 7];
            e7 = ex2f(fmaf(px, qq.x, fmaf(py, qq.y, fmaf(pz, qq.z, qq.w))) + hw);
        }
        s0 += e0; s1 += e1; s2 += e2; s3 += e3;
        s0 += e4; s1 += e5; s2 += e6; s3 += e7;
    }

    ssh[w][lane] = (s0 + s1) + (s2 + s3);
    __syncthreads();

    if (w == 0) {
        float S = ssh[0][lane];
        #pragma unroll
        for (int k = 1; k < NWARP; k++) S += ssh[k][lane];
        ((float*)(io + gi))[3] = pp.w - lg2f(S);   // = -log2N - M0 - lg2(S)
    }
}

// ---------------------------------------------------------------------------
// dist_i = N * sum_j exp2(h1_i + A_j) * C_ij ; C = sq1 + sq2 - (A - h_j)*eps*ln2
// ---------------------------------------------------------------------------
__global__ void __launch_bounds__(TPB, 4) dist_k() {
    __shared__ __align__(16) float4 sj[NP];
    __shared__ float ssq[NP];
    __shared__ float ssh[NWARP][32];

    int lane = threadIdx.x & 31;
    int w    = threadIdx.x >> 5;
    int blk  = blockIdx.x;
    int b    = blk >> 6;
    int base = b * NP;
    int gi   = base + ((blk & 63) << 5) + lane;

    #pragma unroll
    for (int t = 0; t < NP / TPB; t++) {
        int idx = t * TPB + threadIdx.x;
        sj[idx]  = __ldg(g_pk2 + base + idx);
        ssq[idx] = __ldg(g_sq2 + base + idx);
    }

    float4 pp = __ldg(g_pk1 + gi);
    float px = TWOSF * pp.x, py = TWOSF * pp.y, pz = TWOSF * pp.z;
    float tf  = pp.w;
    float sq1 = __ldg(g_sq1 + gi);
    __syncthreads();

    const float4* q  = sj  + w * JCH;
    const float*  r2 = ssq + w * JCH;

    float a0 = 0.f, a1 = 0.f, a2 = 0.f, a3 = 0.f;
    #pragma unroll 1
    for (int j = 0; j < JCH; j += 4) {
        #pragma unroll
        for (int k = 0; k < 4; k++) {
            float4 qq = q[j + k];
            float  A  = fmaf(px, qq.x, fmaf(py, qq.y, fmaf(pz, qq.z, qq.w)));
            float  e  = ex2f(tf + A);
            float  C  = sq1 + r2[j + k] - (A - qq.w) * EPSLN2;
            float  pc = e * C;
            if      (k == 0) a0 += pc;
            else if (k == 1) a1 += pc;
            else if (k == 2) a2 += pc;
            else             a3 += pc;
        }
    }
    ssh[w][lane] = (a0 + a1) + (a2 + a3);
    __syncthreads();

    if (w == 0) {
        float S = ssh[0][lane];
        #pragma unroll
        for (int k = 1; k < NWARP; k++) S += ssh[k][lane];
        float v = sqrtf((float)NP * S + 1e-12f);
        #pragma unroll
        for (int o = 16; o; o >>= 1) v += __shfl_xor_sync(0xffffffffu, v, o);
        if (lane == 0) g_part[blk] = v;
    }
}

// ---------------------------------------------------------------------------
__global__ void finish_k(float* __restrict__ out) {
    __shared__ float sh[BN / 32];
    int t = threadIdx.x;
    sh[t] = g_part[t];
    __syncthreads();
    for (int s = (BN / 32) / 2; s > 0; s >>= 1) {
        if (t < s) sh[t] += sh[t + s];
        __syncthreads();
    }
    if (t == 0) out[0] = sh[0] * (1.0f / (float)BN);
}

// ---------------------------------------------------------------------------
extern "C" void kernel_launch(void* const* d_in, const int* in_sizes, int n_in,
                              void* d_out, int out_size) {
    const float* pc1 = (const float*)d_in[0];
    const float* pc2 = (const float*)d_in[1];
    float* out = (float*)d_out;

    init_k<<<(BN + 255) / 256, 256>>>(pc1, pc2);

    for (int p = 0; p < PHASES; p++) {
        if (p < SAFEP) upd_safe_k<<<BN / 32, TPB>>>(p & 1);
        else           upd_fast_k<<<BN / 32, TPB>>>(p & 1);
    }

    dist_k<<<BN / 32, TPB>>>();
    finish_k<<<1, BN / 32>>>(out);

    (void)in_sizes; (void)n_in; (void)out_size;
}

// round 8
// speedup vs baseline: 1.2984x; 1.0987x over previous
#include <cuda_runtime.h>

// Problem constants
#define NB    8
#define NP    2048
#define BN    (NB * NP)
#define ITERS 50
#define PHASES (2 * ITERS)
#define SAFEP 10                 // warmup phases with online-max (safe) kernel
#define NWARP 8                  // j-split warps per 32-row group
#define JCH   (NP / NWARP)       // 256 j's per warp
#define TPB   (32 * NWARP)

// eps = 0.005
#define SF      288.5390081777927f    // 1/(eps*ln2)
#define TWOSF   577.0780163555854f    // 2/(eps*ln2)
#define EPSLN2  0.0034657359027997264f
#define LOG2NF  11.0f

typedef unsigned long long ULL;

// pk = (x, y, z, h) with h = s*(pot - |p|^2); coords immutable, .w mutated.
__device__ float4 g_pk1[BN], g_pk2[BN];
__device__ float  g_sq1[BN], g_sq2[BN];
__device__ float  g_part[BN / 32];

__device__ __forceinline__ float ex2f(float x) {
    float r; asm("ex2.approx.ftz.f32 %0, %1;" : "=f"(r) : "f"(x)); return r;
}
__device__ __forceinline__ float lg2f(float x) {
    float r; asm("lg2.approx.ftz.f32 %0, %1;" : "=f"(r) : "f"(x)); return r;
}

// ---------------- packed f32x2 helpers ----------------
__device__ __forceinline__ ULL pack2(float lo, float hi) {
    ULL r; asm("mov.b64 %0, {%1, %2};" : "=l"(r) : "f"(lo), "f"(hi)); return r;
}
__device__ __forceinline__ void unpack2(ULL v, float& lo, float& hi) {
    asm("mov.b64 {%0, %1}, %2;" : "=f"(lo), "=f"(hi) : "l"(v));
}
__device__ __forceinline__ ULL fma2(ULL a, ULL b, ULL c) {
    ULL r; asm("fma.rn.f32x2 %0, %1, %2, %3;" : "=l"(r) : "l"(a), "l"(b), "l"(c)); return r;
}
__device__ __forceinline__ ULL add2(ULL a, ULL b) {
    ULL r; asm("add.rn.f32x2 %0, %1, %2;" : "=l"(r) : "l"(a), "l"(b)); return r;
}
// 16B shared load -> two packed j-pairs (SoA)
__device__ __forceinline__ void lds4(const float* sp, ULL& a, ULL& b) {
    unsigned addr = (unsigned)__cvta_generic_to_shared(sp);
    asm volatile("ld.shared.v2.b64 {%0, %1}, [%2];" : "=l"(a), "=l"(b) : "r"(addr));
}

// ---------------------------------------------------------------------------
__global__ void init_k(const float* __restrict__ pc1, const float* __restrict__ pc2) {
    int idx = blockIdx.x * blockDim.x + threadIdx.x;
    if (idx >= BN) return;

    float x = pc1[3 * idx + 0], y = pc1[3 * idx + 1], z = pc1[3 * idx + 2];
    float sq = x * x + y * y + z * z;
    g_pk1[idx] = make_float4(x, y, z, -SF * sq);
    g_sq1[idx] = sq;

    x = pc2[3 * idx + 0]; y = pc2[3 * idx + 1]; z = pc2[3 * idx + 2];
    sq = x * x + y * y + z * z;
    g_pk2[idx] = make_float4(x, y, z, -SF * sq);
    g_sq2[idx] = sq;
}

// ---------------------------------------------------------------------------
// SAFE half-step (warmup): online max, branchless rescale. AoS smem tile.
// ---------------------------------------------------------------------------
__global__ void __launch_bounds__(TPB, 4) upd_safe_k(int dir) {
    const float4* __restrict__ jin = dir ? g_pk1 : g_pk2;
    float4*       __restrict__ io  = dir ? g_pk2 : g_pk1;

    __shared__ __align__(16) float4 sj[NP];
    __shared__ float msh[NWARP][32], ssh[NWARP][32];

    int lane = threadIdx.x & 31;
    int w    = threadIdx.x >> 5;
    int blk  = blockIdx.x;
    int b    = blk >> 6;
    int base = b * NP;
    int gi   = base + ((blk & 63) << 5) + lane;

    #pragma unroll
    for (int t = 0; t < NP / TPB; t++)
        sj[t * TPB + threadIdx.x] = __ldg(jin + base + t * TPB + threadIdx.x);

    float4 pp = __ldg(io + gi);
    float px = TWOSF * pp.x, py = TWOSF * pp.y, pz = TWOSF * pp.z;
    __syncthreads();

    const float4* q = sj + w * JCH;
    float4 q0 = q[0];
    float m  = fmaf(px, q0.x, fmaf(py, q0.y, fmaf(pz, q0.z, q0.w)));
    float s0 = 0.f, s1 = 0.f, s2 = 0.f, s3 = 0.f;

    #pragma unroll 1
    for (int j = 0; j < JCH; j += 8) {
        float A[8];
        #pragma unroll
        for (int k = 0; k < 8; k++) {
            float4 qq = q[j + k];
            A[k] = fmaf(px, qq.x, fmaf(py, qq.y, fmaf(pz, qq.z, qq.w)));
        }
        float c = fmaxf(fmaxf(fmaxf(A[0], A[1]), fmaxf(A[2], A[3])),
                        fmaxf(fmaxf(A[4], A[5]), fmaxf(A[6], A[7])));
        float d  = fmaxf(c - m, 0.0f);
        float sc = ex2f(-d);
        m += d;
        s0 = fmaf(s0, sc, ex2f(A[0] - m));
        s1 = fmaf(s1, sc, ex2f(A[1] - m));
        s2 = fmaf(s2, sc, ex2f(A[2] - m));
        s3 = fmaf(s3, sc, ex2f(A[3] - m));
        s0 += ex2f(A[4] - m);
        s1 += ex2f(A[5] - m);
        s2 += ex2f(A[6] - m);
        s3 += ex2f(A[7] - m);
    }

    msh[w][lane] = m;
    ssh[w][lane] = (s0 + s1) + (s2 + s3);
    __syncthreads();

    if (w == 0) {
        float M = msh[0][lane];
        #pragma unroll
        for (int k = 1; k < NWARP; k++) M = fmaxf(M, msh[k][lane]);
        float S = 0.f;
        #pragma unroll
        for (int k = 0; k < NWARP; k++) S += ssh[k][lane] * ex2f(msh[k][lane] - M);
        ((float*)(io + gi))[3] = -LOG2NF - M - lg2f(S);
    }
}

// ---------------------------------------------------------------------------
// FAST half-step: fixed per-row reference M0 = -h_old - log2N (exact identity
// h_new = h_old - lg2 sum_j 2^(A_j + h_old + log2N)). SoA smem tile
// (transposed during staging) -> ld.shared.v2.b64 yields packed j-pairs,
// inner math in f32x2: per 4 j = 4 LDS + 8 f32x2 + 2 MOV + 4 EX2 + 4 FADD.
// ---------------------------------------------------------------------------
__global__ void __launch_bounds__(TPB, 4) upd_fast_k(int dir) {
    const float4* __restrict__ jin = dir ? g_pk1 : g_pk2;
    float4*       __restrict__ io  = dir ? g_pk2 : g_pk1;

    __shared__ __align__(16) float sx[NP], sy[NP], sz[NP], shh[NP];
    __shared__ float ssh[NWARP][32];

    int lane = threadIdx.x & 31;
    int w    = threadIdx.x >> 5;
    int blk  = blockIdx.x;
    int b    = blk >> 6;
    int base = b * NP;
    int gi   = base + ((blk & 63) << 5) + lane;

    // stage j-side, AoS global -> SoA smem (STS conflict-free: consecutive idx)
    #pragma unroll
    for (int t = 0; t < NP / TPB; t++) {
        int idx = t * TPB + threadIdx.x;
        float4 v = __ldg(jin + base + idx);
        sx[idx] = v.x; sy[idx] = v.y; sz[idx] = v.z; shh[idx] = v.w;
    }

    float4 pp = __ldg(io + gi);
    float px = TWOSF * pp.x, py = TWOSF * pp.y, pz = TWOSF * pp.z;
    float hw = pp.w + LOG2NF;             // -M0
    __syncthreads();

    const float* qx = sx  + w * JCH;
    const float* qy = sy  + w * JCH;
    const float* qz = sz  + w * JCH;
    const float* qh = shh + w * JCH;

    ULL px2 = pack2(px, px), py2 = pack2(py, py), pz2 = pack2(pz, pz);
    ULL hw2 = pack2(hw, hw);

    float s0 = 0.f, s1 = 0.f, s2 = 0.f, s3 = 0.f;

    #pragma unroll 2
    for (int j = 0; j < JCH; j += 8) {
        #pragma unroll
        for (int u = 0; u < 2; u++) {
            int jj = j + u * 4;
            ULL x01, x23, y01, y23, z01, z23, h01, h23;
            lds4(qx + jj, x01, x23);
            lds4(qy + jj, y01, y23);
            lds4(qz + jj, z01, z23);
            lds4(qh + jj, h01, h23);

            ULL A01 = fma2(px2, x01, fma2(py2, y01, fma2(pz2, z01, add2(h01, hw2))));
            ULL A23 = fma2(px2, x23, fma2(py2, y23, fma2(pz2, z23, add2(h23, hw2))));

            float a0, a1, a2, a3;
            unpack2(A01, a0, a1);
            unpack2(A23, a2, a3);
            s0 += ex2f(a0);
            s1 += ex2f(a1);
            s2 += ex2f(a2);
            s3 += ex2f(a3);
        }
    }

    ssh[w][lane] = (s0 + s1) + (s2 + s3);
    __syncthreads();

    if (w == 0) {
        float S = ssh[0][lane];
        #pragma unroll
        for (int k = 1; k < NWARP; k++) S += ssh[k][lane];
        ((float*)(io + gi))[3] = pp.w - lg2f(S);   // = -log2N - M0 - lg2(S)
    }
}

// ---------------------------------------------------------------------------
// dist_i = N * sum_j exp2(h1_i + A_j) * C_ij ; C = sq1 + sq2 - (A - h_j)*eps*ln2
// ---------------------------------------------------------------------------
__global__ void __launch_bounds__(TPB, 4) dist_k() {
    __shared__ __align__(16) float4 sj[NP];
    __shared__ float ssq[NP];
    __shared__ float ssh[NWARP][32];

    int lane = threadIdx.x & 31;
    int w    = threadIdx.x >> 5;
    int blk  = blockIdx.x;
    int b    = blk >> 6;
    int base = b * NP;
    int gi   = base + ((blk & 63) << 5) + lane;

    #pragma unroll
    for (int t = 0; t < NP / TPB; t++) {
        int idx = t * TPB + threadIdx.x;
        sj[idx]  = __ldg(g_pk2 + base + idx);
        ssq[idx] = __ldg(g_sq2 + base + idx);
    }

    float4 pp = __ldg(g_pk1 + gi);
    float px = TWOSF * pp.x, py = TWOSF * pp.y, pz = TWOSF * pp.z;
    float tf  = pp.w;
    float sq1 = __ldg(g_sq1 + gi);
    __syncthreads();

    const float4* q  = sj  + w * JCH;
    const float*  r2 = ssq + w * JCH;

    float a0 = 0.f, a1 = 0.f, a2 = 0.f, a3 = 0.f;
    #pragma unroll 1
    for (int j = 0; j < JCH; j += 4) {
        #pragma unroll
        for (int k = 0; k < 4; k++) {
            float4 qq = q[j + k];
            float  A  = fmaf(px, qq.x, fmaf(py, qq.y, fmaf(pz, qq.z, qq.w)));
            float  e  = ex2f(tf + A);
            float  C  = sq1 + r2[j + k] - (A - qq.w) * EPSLN2;
            float  pc = e * C;
            if      (k == 0) a0 += pc;
            else if (k == 1) a1 += pc;
            else if (k == 2) a2 += pc;
            else             a3 += pc;
        }
    }
    ssh[w][lane] = (a0 + a1) + (a2 + a3);
    __syncthreads();

    if (w == 0) {
        float S = ssh[0][lane];
        #pragma unroll
        for (int k = 1; k < NWARP; k++) S += ssh[k][lane];
        float v = sqrtf((float)NP * S + 1e-12f);
        #pragma unroll
        for (int o = 16; o; o >>= 1) v += __shfl_xor_sync(0xffffffffu, v, o);
        if (lane == 0) g_part[blk] = v;
    }
}

// ---------------------------------------------------------------------------
__global__ void finish_k(float* __restrict__ out) {
    __shared__ float sh[BN / 32];
    int t = threadIdx.x;
    sh[t] = g_part[t];
    __syncthreads();
    for (int s = (BN / 32) / 2; s > 0; s >>= 1) {
        if (t < s) sh[t] += sh[t + s];
        __syncthreads();
    }
    if (t == 0) out[0] = sh[0] * (1.0f / (float)BN);
}

// ---------------------------------------------------------------------------
extern "C" void kernel_launch(void* const* d_in, const int* in_sizes, int n_in,
                              void* d_out, int out_size) {
    const float* pc1 = (const float*)d_in[0];
    const float* pc2 = (const float*)d_in[1];
    float* out = (float*)d_out;

    init_k<<<(BN + 255) / 256, 256>>>(pc1, pc2);

    for (int p = 0; p < PHASES; p++) {
        if (p < SAFEP) upd_safe_k<<<BN / 32, TPB>>>(p & 1);
        else           upd_fast_k<<<BN / 32, TPB>>>(p & 1);
    }

    dist_k<<<BN / 32, TPB>>>();
    finish_k<<<1, BN / 32>>>(out);

    (void)in_sizes; (void)n_in; (void)out_size;
}

// round 9
// speedup vs baseline: 1.3327x; 1.0265x over previous
#include <cuda_runtime.h>

// Problem constants
#define NB    8
#define NP    2048
#define BN    (NB * NP)
#define ITERS 50
#define PHASES (2 * ITERS)
#define NWARP 8                  // j-split warps per 32-row group
#define JCH   (NP / NWARP)       // 256 j's per warp
#define TPB   (32 * NWARP)

// eps = 0.005
#define SF      288.5390081777927f    // 1/(eps*ln2)
#define TWOSF   577.0780163555854f    // 2/(eps*ln2)
#define EPSLN2  0.0034657359027997264f
#define LOG2NF  11.0f

typedef unsigned long long ULL;

// pk = (x, y, z, h) with h = s*(pot - |p|^2); coords immutable, .w mutated.
__device__ float4 g_pk1[BN], g_pk2[BN];
__device__ float  g_sq1[BN], g_sq2[BN];
__device__ float  g_part[BN / 32];

__device__ __forceinline__ float ex2f(float x) {
    float r; asm("ex2.approx.ftz.f32 %0, %1;" : "=f"(r) : "f"(x)); return r;
}
__device__ __forceinline__ float lg2f(float x) {
    float r; asm("lg2.approx.ftz.f32 %0, %1;" : "=f"(r) : "f"(x)); return r;
}

// ---------------- packed f32x2 helpers ----------------
__device__ __forceinline__ ULL pack2(float lo, float hi) {
    ULL r; asm("mov.b64 %0, {%1, %2};" : "=l"(r) : "f"(lo), "f"(hi)); return r;
}
__device__ __forceinline__ void unpack2(ULL v, float& lo, float& hi) {
    asm("mov.b64 {%0, %1}, %2;" : "=f"(lo), "=f"(hi) : "l"(v));
}
__device__ __forceinline__ ULL fma2(ULL a, ULL b, ULL c) {
    ULL r; asm("fma.rn.f32x2 %0, %1, %2, %3;" : "=l"(r) : "l"(a), "l"(b), "l"(c)); return r;
}
__device__ __forceinline__ ULL add2(ULL a, ULL b) {
    ULL r; asm("add.rn.f32x2 %0, %1, %2;" : "=l"(r) : "l"(a), "l"(b)); return r;
}
// 16B shared load -> two packed j-pairs (SoA)
__device__ __forceinline__ void lds4(const float* sp, ULL& a, ULL& b) {
    unsigned addr = (unsigned)__cvta_generic_to_shared(sp);
    asm volatile("ld.shared.v2.b64 {%0, %1}, [%2];" : "=l"(a), "=l"(b) : "r"(addr));
}

// ---------------------------------------------------------------------------
__global__ void init_k(const float* __restrict__ pc1, const float* __restrict__ pc2) {
    int idx = blockIdx.x * blockDim.x + threadIdx.x;
    if (idx >= BN) return;

    float x = pc1[3 * idx + 0], y = pc1[3 * idx + 1], z = pc1[3 * idx + 2];
    float sq = x * x + y * y + z * z;
    g_pk1[idx] = make_float4(x, y, z, -SF * sq);
    g_sq1[idx] = sq;

    x = pc2[3 * idx + 0]; y = pc2[3 * idx + 1]; z = pc2[3 * idx + 2];
    sq = x * x + y * y + z * z;
    g_pk2[idx] = make_float4(x, y, z, -SF * sq);
    g_sq2[idx] = sq;
}

// ---------------------------------------------------------------------------
// Half-step with fixed-reference fast path + warp rescue.
//   A_j = 2s p_i . q_j + h_j ; x_j = A_j + hw, hw = h_old + log2N = -M0
//   fast: S = sum_j 2^x_j  ->  (m, s) = (M0, S)
//   rescue (any lane S invalid): exact online-max over the chunk
//   merge (log domain): h_new = -log2N - M - lg2( sum_w s_w 2^(m_w - M) )
// Per-warp staging of own j-chunk (no block barrier before the mainloop).
// ---------------------------------------------------------------------------
__global__ void __launch_bounds__(TPB, 4) upd_k(int dir) {
    const float4* __restrict__ jin = dir ? g_pk1 : g_pk2;
    float4*       __restrict__ io  = dir ? g_pk2 : g_pk1;

    __shared__ __align__(16) float sx[NP], sy[NP], sz[NP], shh[NP];
    __shared__ float msh[NWARP][32], ssh[NWARP][32];

    int lane = threadIdx.x & 31;
    int w    = threadIdx.x >> 5;
    int blk  = blockIdx.x;
    int b    = blk >> 6;
    int base = b * NP;
    int gi   = base + ((blk & 63) << 5) + lane;

    // Per-warp staging: warp w stages only its own chunk.
    // lane -> j = lane + 32k : coalesced LDG.128, conflict-free STS.
    {
        const float4* src = jin + base + w * JCH;
        #pragma unroll
        for (int k = 0; k < JCH / 32; k++) {
            float4 v = __ldg(src + lane + 32 * k);
            int idx = w * JCH + lane + 32 * k;
            sx[idx] = v.x; sy[idx] = v.y; sz[idx] = v.z; shh[idx] = v.w;
        }
    }

    float4 pp = __ldg(io + gi);
    float px = TWOSF * pp.x, py = TWOSF * pp.y, pz = TWOSF * pp.z;
    float hw = pp.w + LOG2NF;             // -M0
    __syncwarp();

    const float* qx = sx  + w * JCH;
    const float* qy = sy  + w * JCH;
    const float* qz = sz  + w * JCH;
    const float* qh = shh + w * JCH;

    ULL px2 = pack2(px, px), py2 = pack2(py, py), pz2 = pack2(pz, pz);
    ULL hw2 = pack2(hw, hw);

    float s0 = 0.f, s1 = 0.f, s2 = 0.f, s3 = 0.f;

    #pragma unroll 2
    for (int j = 0; j < JCH; j += 8) {
        #pragma unroll
        for (int u = 0; u < 2; u++) {
            int jj = j + u * 4;
            ULL x01, x23, y01, y23, z01, z23, h01, h23;
            lds4(qx + jj, x01, x23);
            lds4(qy + jj, y01, y23);
            lds4(qz + jj, z01, z23);
            lds4(qh + jj, h01, h23);

            ULL A01 = fma2(px2, x01, fma2(py2, y01, fma2(pz2, z01, add2(h01, hw2))));
            ULL A23 = fma2(px2, x23, fma2(py2, y23, fma2(pz2, z23, add2(h23, hw2))));

            float a0, a1, a2, a3;
            unpack2(A01, a0, a1);
            unpack2(A23, a2, a3);
            s0 += ex2f(a0);
            s1 += ex2f(a1);
            s2 += ex2f(a2);
            s3 += ex2f(a3);
        }
    }

    float S = (s0 + s1) + (s2 + s3);
    float m_out = -hw;                    // M0
    float s_out = S;

    // Rescue: any lane with overflow (inf/NaN) or total-underflow (S==0)
    // re-runs the chunk with the exact online-max recurrence (whole warp).
    bool ok = (S > 0.0f) && (S <= 3.3e38f);
    if (__ballot_sync(0xffffffffu, !ok)) {
        float m = -1e30f, s = 0.f;
        for (int j = 0; j < JCH; j++) {
            float A  = fmaf(px, qx[j], fmaf(py, qy[j], fmaf(pz, qz[j], qh[j])));
            float mn = fmaxf(A, m);
            s = s * ex2f(m - mn) + ex2f(A - mn);
            m = mn;
        }
        m_out = m;
        s_out = s;
    }

    msh[w][lane] = m_out;
    ssh[w][lane] = s_out;
    __syncthreads();

    if (w == 0) {
        float M = msh[0][lane];
        #pragma unroll
        for (int k = 1; k < NWARP; k++) M = fmaxf(M, msh[k][lane]);
        float Sm = 0.f;
        #pragma unroll
        for (int k = 0; k < NWARP; k++) Sm += ssh[k][lane] * ex2f(msh[k][lane] - M);
        ((float*)(io + gi))[3] = -LOG2NF - M - lg2f(Sm);
    }
}

// ---------------------------------------------------------------------------
// dist_i = N * sum_j exp2(h1_i + A_j) * C_ij ; C = sq1 + sq2 - (A - h_j)*eps*ln2
// Per-warp staging, AoS tile.
// ---------------------------------------------------------------------------
__global__ void __launch_bounds__(TPB, 4) dist_k() {
    __shared__ __align__(16) float4 sj[NP];
    __shared__ float ssq[NP];
    __shared__ float ssh[NWARP][32];

    int lane = threadIdx.x & 31;
    int w    = threadIdx.x >> 5;
    int blk  = blockIdx.x;
    int b    = blk >> 6;
    int base = b * NP;
    int gi   = base + ((blk & 63) << 5) + lane;

    {
        const float4* src = g_pk2 + base + w * JCH;
        const float*  srq = g_sq2 + base + w * JCH;
        #pragma unroll
        for (int k = 0; k < JCH / 32; k++) {
            int idx = w * JCH + lane + 32 * k;
            sj[idx]  = __ldg(src + lane + 32 * k);
            ssq[idx] = __ldg(srq + lane + 32 * k);
        }
    }

    float4 pp = __ldg(g_pk1 + gi);
    float px = TWOSF * pp.x, py = TWOSF * pp.y, pz = TWOSF * pp.z;
    float tf  = pp.w;
    float sq1 = __ldg(g_sq1 + gi);
    __syncwarp();

    const float4* q  = sj  + w * JCH;
    const float*  r2 = ssq + w * JCH;

    float a0 = 0.f, a1 = 0.f, a2 = 0.f, a3 = 0.f;
    #pragma unroll 1
    for (int j = 0; j < JCH; j += 4) {
        #pragma unroll
        for (int k = 0; k < 4; k++) {
            float4 qq = q[j + k];
            float  A  = fmaf(px, qq.x, fmaf(py, qq.y, fmaf(pz, qq.z, qq.w)));
            float  e  = ex2f(tf + A);
            float  C  = sq1 + r2[j + k] - (A - qq.w) * EPSLN2;
            float  pc = e * C;
            if      (k == 0) a0 += pc;
            else if (k == 1) a1 += pc;
            else if (k == 2) a2 += pc;
            else             a3 += pc;
        }
    }
    ssh[w][lane] = (a0 + a1) + (a2 + a3);
    __syncthreads();

    if (w == 0) {
        float S = ssh[0][lane];
        #pragma unroll
        for (int k = 1; k < NWARP; k++) S += ssh[k][lane];
        float v = sqrtf((float)NP * S + 1e-12f);
        #pragma unroll
        for (int o = 16; o; o >>= 1) v += __shfl_xor_sync(0xffffffffu, v, o);
        if (lane == 0) g_part[blk] = v;
    }
}

// ---------------------------------------------------------------------------
__global__ void finish_k(float* __restrict__ out) {
    __shared__ float sh[BN / 32];
    int t = threadIdx.x;
    sh[t] = g_part[t];
    __syncthreads();
    for (int s = (BN / 32) / 2; s > 0; s >>= 1) {
        if (t < s) sh[t] += sh[t + s];
        __syncthreads();
    }
    if (t == 0) out[0] = sh[0] * (1.0f / (float)BN);
}

// ---------------------------------------------------------------------------
extern "C" void kernel_launch(void* const* d_in, const int* in_sizes, int n_in,
                              void* d_out, int out_size) {
    const float* pc1 = (const float*)d_in[0];
    const float* pc2 = (const float*)d_in[1];
    float* out = (float*)d_out;

    init_k<<<(BN + 255) / 256, 256>>>(pc1, pc2);

    for (int p = 0; p < PHASES; p++)
        upd_k<<<BN / 32, TPB>>>(p & 1);

    dist_k<<<BN / 32, TPB>>>();
    finish_k<<<1, BN / 32>>>(out);

    (void)in_sizes; (void)n_in; (void)out_size;
}

// round 10
// speedup vs baseline: 1.3349x; 1.0016x over previous
#include <cuda_runtime.h>

// Problem constants
#define NB     8
#define NP     2048
#define BN     (NB * NP)
#define ITERS  50
#define PHASES (2 * ITERS)
#define NWARP  8
#define JCH    (NP / NWARP)      // 256 j's per warp
#define TPB    256
#define GRID   512
#define BPB    64                // blocks per batch

// eps = 0.005
#define SF      288.5390081777927f    // 1/(eps*ln2)
#define TWOSF   577.0780163555854f    // 2/(eps*ln2)
#define EPSLN2  0.0034657359027997264f
#define LOG2NF  11.0f

typedef unsigned long long ULL;

// Global SoA state. h = s*(pot - |p|^2), s = 1/(eps ln2). Coords immutable.
__device__ float g_x1[BN], g_y1[BN], g_z1[BN], g_h1[BN], g_sq1[BN];
__device__ float g_x2[BN], g_y2[BN], g_z2[BN], g_h2[BN], g_sq2[BN];
__device__ float    g_part[GRID];
__device__ unsigned g_barr[NB * 32];   // per-batch arrive counters (128B apart)
__device__ unsigned g_brel[NB * 32];   // per-batch release epochs
__device__ unsigned g_fin;             // final arrive counter

// ---------------- helpers ----------------
__device__ __forceinline__ float ex2f(float x) {
    float r; asm("ex2.approx.ftz.f32 %0, %1;" : "=f"(r) : "f"(x)); return r;
}
__device__ __forceinline__ float lg2f(float x) {
    float r; asm("lg2.approx.ftz.f32 %0, %1;" : "=f"(r) : "f"(x)); return r;
}
__device__ __forceinline__ ULL pack2(float lo, float hi) {
    ULL r; asm("mov.b64 %0, {%1, %2};" : "=l"(r) : "f"(lo), "f"(hi)); return r;
}
__device__ __forceinline__ void unpack2(ULL v, float& lo, float& hi) {
    asm("mov.b64 {%0, %1}, %2;" : "=f"(lo), "=f"(hi) : "l"(v));
}
__device__ __forceinline__ ULL fma2(ULL a, ULL b, ULL c) {
    ULL r; asm("fma.rn.f32x2 %0, %1, %2, %3;" : "=l"(r) : "l"(a), "l"(b), "l"(c)); return r;
}
__device__ __forceinline__ ULL add2(ULL a, ULL b) {
    ULL r; asm("add.rn.f32x2 %0, %1, %2;" : "=l"(r) : "l"(a), "l"(b)); return r;
}
__device__ __forceinline__ void lds4(const float* sp, ULL& a, ULL& b) {
    unsigned addr = (unsigned)__cvta_generic_to_shared(sp);
    asm volatile("ld.shared.v2.b64 {%0, %1}, [%2];" : "=l"(a), "=l"(b) : "r"(addr));
}
__device__ __forceinline__ unsigned ld_acq(const unsigned* p) {
    unsigned v; asm volatile("ld.acquire.gpu.global.u32 %0, [%1];" : "=r"(v) : "l"(p) : "memory"); return v;
}
__device__ __forceinline__ unsigned atom_add_rel(unsigned* p, unsigned v) {
    unsigned o; asm volatile("atom.release.gpu.global.add.u32 %0, [%1], %2;" : "=r"(o) : "l"(p), "r"(v) : "memory"); return o;
}
__device__ __forceinline__ void st_rel(unsigned* p, unsigned v) {
    asm volatile("st.release.gpu.global.u32 [%0], %1;" :: "l"(p), "r"(v) : "memory");
}
__device__ __forceinline__ float4 ldcg4(const float4* p) {
    float4 r; asm volatile("ld.global.cg.v4.f32 {%0,%1,%2,%3}, [%4];"
        : "=f"(r.x), "=f"(r.y), "=f"(r.z), "=f"(r.w) : "l"(p)); return r;
}
__device__ __forceinline__ float ldcgf(const float* p) {
    float r; asm volatile("ld.global.cg.f32 %0, [%1];" : "=f"(r) : "l"(p)); return r;
}
__device__ __forceinline__ void stcgf(float* p, float v) {
    asm volatile("st.global.cg.f32 [%0], %1;" :: "l"(p), "f"(v));
}

// Per-batch grid barrier (BPB blocks). Monotonic epoch counter from 1.
__device__ __forceinline__ void batch_barrier(int b, unsigned epoch) {
    __threadfence();
    __syncthreads();
    if (threadIdx.x == 0) {
        unsigned* cnt = &g_barr[b * 32];
        unsigned* rel = &g_brel[b * 32];
        unsigned old = atom_add_rel(cnt, 1u);
        if (old == epoch * (unsigned)BPB - 1u) st_rel(rel, epoch);
        else while (ld_acq(rel) < epoch) __nanosleep(32);
    }
    __syncthreads();
}

// ---------------------------------------------------------------------------
// One persistent kernel. 512 blocks = 8 batches x 64 row-groups of 32 rows.
// Per block: row constants in registers for all phases; smem holds the
// j-side coord tile (prefetched for the NEXT phase during barrier wait) and
// the per-phase h tile (8KB .cg reload). Fast fixed-reference LSE with warp
// rescue; dist + deterministic reduce at the end.
// ---------------------------------------------------------------------------
__global__ void __launch_bounds__(TPB, 4) emd_k(
    const float* __restrict__ pc1, const float* __restrict__ pc2,
    float* __restrict__ out)
{
    __shared__ __align__(16) float sx[NP], sy[NP], sz[NP], shh[NP], ssq[NP];
    __shared__ float msh[NWARP][32], ssh[NWARP][32];
    __shared__ float red[TPB];

    const int tid  = threadIdx.x;
    const int lane = tid & 31;
    const int w    = tid >> 5;
    const int blk  = blockIdx.x;
    const int b    = blk >> 6;
    const int base = b * NP;
    const int gi   = base + ((blk & 63) << 5) + lane;
    const int o4   = (w * JCH) >> 2;          // float4 offset of warp's chunk

    // ---- init: this block's 32 rows, both sets (SoA) ----
    if (tid < 32) {
        int r = base + ((blk & 63) << 5) + tid;
        float x = pc1[3 * r], y = pc1[3 * r + 1], z = pc1[3 * r + 2];
        float sq = x * x + y * y + z * z;
        g_x1[r] = x; g_y1[r] = y; g_z1[r] = z; g_sq1[r] = sq; g_h1[r] = -SF * sq;
        x = pc2[3 * r]; y = pc2[3 * r + 1]; z = pc2[3 * r + 2];
        sq = x * x + y * y + z * z;
        g_x2[r] = x; g_y2[r] = y; g_z2[r] = z; g_sq2[r] = sq; g_h2[r] = -SF * sq;
    }

    // ---- row constants (registers for the whole run) ----
    float r1x = pc1[3 * gi], r1y = pc1[3 * gi + 1], r1z = pc1[3 * gi + 2];
    float sq1 = r1x * r1x + r1y * r1y + r1z * r1z;
    float px1 = TWOSF * r1x, py1 = TWOSF * r1y, pz1 = TWOSF * r1z;
    float r2x = pc2[3 * gi], r2y = pc2[3 * gi + 1], r2z = pc2[3 * gi + 2];
    float px2 = TWOSF * r2x, py2 = TWOSF * r2y, pz2 = TWOSF * r2z;

    batch_barrier(b, 1);

    // ---- stage coords for phase 0 (j = set2), per-warp chunk ----
    #pragma unroll
    for (int k = 0; k < 2; k++) {
        ((float4*)sx)[o4 + lane + 32 * k] = __ldg((const float4*)(g_x2 + base) + o4 + lane + 32 * k);
        ((float4*)sy)[o4 + lane + 32 * k] = __ldg((const float4*)(g_y2 + base) + o4 + lane + 32 * k);
        ((float4*)sz)[o4 + lane + 32 * k] = __ldg((const float4*)(g_z2 + base) + o4 + lane + 32 * k);
    }

    // ---- phases 0..99 = Sinkhorn half-steps; phase 100 = dist ----
    #pragma unroll 1
    for (int p = 0; p <= PHASES; p++) {
        const int par = p & 1;                 // 0: j=set2, rows=set1

        // stage j-side h (fresh, through L2) per warp
        const float* jh = par ? g_h1 : g_h2;
        #pragma unroll
        for (int k = 0; k < 2; k++)
            ((float4*)shh)[o4 + lane + 32 * k] = ldcg4((const float4*)(jh + base) + o4 + lane + 32 * k);
        if (p == PHASES) {
            #pragma unroll
            for (int k = 0; k < 2; k++)
                ((float4*)ssq)[o4 + lane + 32 * k] = __ldg((const float4*)(g_sq2 + base) + o4 + lane + 32 * k);
        }
        __syncwarp();

        const float* qx = sx  + w * JCH;
        const float* qy = sy  + w * JCH;
        const float* qz = sz  + w * JCH;
        const float* qh = shh + w * JCH;

        if (p < PHASES) {
            float px = par ? px2 : px1, py = par ? py2 : py1, pz = par ? pz2 : pz1;
            float* ho = par ? g_h2 : g_h1;
            float h_old = ldcgf(ho + gi);
            float hw = h_old + LOG2NF;         // -M0

            ULL px_2 = pack2(px, px), py_2 = pack2(py, py), pz_2 = pack2(pz, pz);
            ULL hw_2 = pack2(hw, hw);
            float s0 = 0.f, s1 = 0.f, s2 = 0.f, s3 = 0.f;

            #pragma unroll 2
            for (int j = 0; j < JCH; j += 8) {
                #pragma unroll
                for (int u = 0; u < 2; u++) {
                    int jj = j + u * 4;
                    ULL x01, x23, y01, y23, z01, z23, h01, h23;
                    lds4(qx + jj, x01, x23);
                    lds4(qy + jj, y01, y23);
                    lds4(qz + jj, z01, z23);
                    lds4(qh + jj, h01, h23);
                    ULL A01 = fma2(px_2, x01, fma2(py_2, y01, fma2(pz_2, z01, add2(h01, hw_2))));
                    ULL A23 = fma2(px_2, x23, fma2(py_2, y23, fma2(pz_2, z23, add2(h23, hw_2))));
                    float a0, a1, a2, a3;
                    unpack2(A01, a0, a1);
                    unpack2(A23, a2, a3);
                    s0 += ex2f(a0);
                    s1 += ex2f(a1);
                    s2 += ex2f(a2);
                    s3 += ex2f(a3);
                }
            }
            float S = (s0 + s1) + (s2 + s3);
            float m_out = -hw, s_out = S;

            // warp rescue: exact online-max if any lane over/underflowed
            bool ok = (S > 0.0f) && (S <= 3.3e38f);
            if (__ballot_sync(0xffffffffu, !ok)) {
                float m = -1e30f, s = 0.f;
                for (int j = 0; j < JCH; j++) {
                    float A  = fmaf(px, qx[j], fmaf(py, qy[j], fmaf(pz, qz[j], qh[j])));
                    float mn = fmaxf(A, m);
                    s = s * ex2f(m - mn) + ex2f(A - mn);
                    m = mn;
                }
                m_out = m; s_out = s;
            }

            msh[w][lane] = m_out;
            ssh[w][lane] = s_out;
            __syncthreads();

            if (w == 0) {
                float M = msh[0][lane];
                #pragma unroll
                for (int k = 1; k < NWARP; k++) M = fmaxf(M, msh[k][lane]);
                float Sm = 0.f;
                #pragma unroll
                for (int k = 0; k < NWARP; k++) Sm += ssh[k][lane] * ex2f(msh[k][lane] - M);
                stcgf(ho + gi, -LOG2NF - M - lg2f(Sm));
            }

            // prefetch NEXT phase's coord tile (immutable) -> hides in barrier
            {
                const float* nx = ((p + 1) & 1) ? g_x1 : g_x2;
                const float* ny = ((p + 1) & 1) ? g_y1 : g_y2;
                const float* nz = ((p + 1) & 1) ? g_z1 : g_z2;
                #pragma unroll
                for (int k = 0; k < 2; k++) {
                    ((float4*)sx)[o4 + lane + 32 * k] = __ldg((const float4*)(nx + base) + o4 + lane + 32 * k);
                    ((float4*)sy)[o4 + lane + 32 * k] = __ldg((const float4*)(ny + base) + o4 + lane + 32 * k);
                    ((float4*)sz)[o4 + lane + 32 * k] = __ldg((const float4*)(nz + base) + o4 + lane + 32 * k);
                }
            }
            batch_barrier(b, (unsigned)(p + 2));
        } else {
            // ---- dist: rows = set1, j = set2 (coords/h2/sq2 staged) ----
            float tf = ldcgf(g_h1 + gi);
            const float* qs = ssq + w * JCH;
            float a0 = 0.f, a1 = 0.f, a2 = 0.f, a3 = 0.f;
            #pragma unroll 1
            for (int j = 0; j < JCH; j += 4) {
                #pragma unroll
                for (int k = 0; k < 4; k++) {
                    float hj = qh[j + k];
                    float A  = fmaf(px1, qx[j + k], fmaf(py1, qy[j + k], fmaf(pz1, qz[j + k], hj)));
                    float e  = ex2f(tf + A);
                    float C  = sq1 + qs[j + k] - (A - hj) * EPSLN2;
                    float pc = e * C;
                    if      (k == 0) a0 += pc;
                    else if (k == 1) a1 += pc;
                    else if (k == 2) a2 += pc;
                    else             a3 += pc;
                }
            }
            ssh[w][lane] = (a0 + a1) + (a2 + a3);
            __syncthreads();
            if (w == 0) {
                float S = ssh[0][lane];
                #pragma unroll
                for (int k = 1; k < NWARP; k++) S += ssh[k][lane];
                float v = sqrtf((float)NP * S + 1e-12f);
                #pragma unroll
                for (int o = 16; o; o >>= 1) v += __shfl_xor_sync(0xffffffffu, v, o);
                if (lane == 0) stcgf(&g_part[blk], v);
            }
        }
    }

    // ---- final: all blocks arrive; block 0 reduces deterministically ----
    __threadfence();
    __syncthreads();
    if (tid == 0) atom_add_rel(&g_fin, 1u);
    if (blk != 0) return;

    if (tid == 0) { while (ld_acq(&g_fin) < (unsigned)GRID) __nanosleep(32); }
    __syncthreads();

    red[tid] = ldcgf(&g_part[tid]) + ldcgf(&g_part[tid + TPB]);
    __syncthreads();
    #pragma unroll
    for (int s = TPB / 2; s > 0; s >>= 1) {
        if (tid < s) red[tid] += red[tid + s];
        __syncthreads();
    }
    if (tid == 0) {
        out[0] = red[0] * (1.0f / (float)BN);
        // reset barrier state for the next graph replay
        g_fin = 0;
        #pragma unroll
        for (int k = 0; k < NB; k++) { g_barr[k * 32] = 0; g_brel[k * 32] = 0; }
    }
}

// ---------------------------------------------------------------------------
extern "C" void kernel_launch(void* const* d_in, const int* in_sizes, int n_in,
                              void* d_out, int out_size) {
    const float* pc1 = (const float*)d_in[0];
    const float* pc2 = (const float*)d_in[1];
    float* out = (float*)d_out;

    emd_k<<<GRID, TPB>>>(pc1, pc2, out);

    (void)in_sizes; (void)n_in; (void)out_size;
}

// round 11
// speedup vs baseline: 1.4937x; 1.1189x over previous
#include <cuda_runtime.h>

// Problem constants
#define NB    8
#define NP    2048
#define BN    (NB * NP)
#define ITERS 50
#define PHASES (2 * ITERS)

// upd kernel shape: 256 blocks x 512 threads; 64 rows/block (2 rows/lane),
// 16 warps each owning a 128-j chunk.
#define UWARP 16
#define UJCH  (NP / UWARP)       // 128
#define UTPB  (32 * UWARP)       // 512
#define UGRID (BN / 64)          // 256

// dist kernel shape (runs once): 512 blocks x 256 threads, 32 rows/block
#define DWARP 8
#define DJCH  (NP / DWARP)       // 256
#define DTPB  (32 * DWARP)       // 256

// eps = 0.005
#define SF      288.5390081777927f    // 1/(eps*ln2)
#define TWOSF   577.0780163555854f    // 2/(eps*ln2)
#define EPSLN2  0.0034657359027997264f
#define LOG2NF  11.0f

typedef unsigned long long ULL;

// Global SoA state. h = s*(pot - |p|^2), s = 1/(eps ln2). Coords immutable.
__device__ float g_x1[BN], g_y1[BN], g_z1[BN], g_h1[BN], g_sq1[BN];
__device__ float g_x2[BN], g_y2[BN], g_z2[BN], g_h2[BN], g_sq2[BN];
__device__ float g_part[BN / 32];

// ---------------- helpers ----------------
__device__ __forceinline__ float ex2f(float x) {
    float r; asm("ex2.approx.ftz.f32 %0, %1;" : "=f"(r) : "f"(x)); return r;
}
__device__ __forceinline__ float lg2f(float x) {
    float r; asm("lg2.approx.ftz.f32 %0, %1;" : "=f"(r) : "f"(x)); return r;
}
__device__ __forceinline__ ULL pack2(float lo, float hi) {
    ULL r; asm("mov.b64 %0, {%1, %2};" : "=l"(r) : "f"(lo), "f"(hi)); return r;
}
__device__ __forceinline__ void unpack2(ULL v, float& lo, float& hi) {
    asm("mov.b64 {%0, %1}, %2;" : "=f"(lo), "=f"(hi) : "l"(v));
}
__device__ __forceinline__ ULL fma2(ULL a, ULL b, ULL c) {
    ULL r; asm("fma.rn.f32x2 %0, %1, %2, %3;" : "=l"(r) : "l"(a), "l"(b), "l"(c)); return r;
}
__device__ __forceinline__ ULL add2(ULL a, ULL b) {
    ULL r; asm("add.rn.f32x2 %0, %1, %2;" : "=l"(r) : "l"(a), "l"(b)); return r;
}
// 16B shared load -> two packed j-pairs (SoA)
__device__ __forceinline__ void lds4(const float* sp, ULL& a, ULL& b) {
    unsigned addr = (unsigned)__cvta_generic_to_shared(sp);
    asm volatile("ld.shared.v2.b64 {%0, %1}, [%2];" : "=l"(a), "=l"(b) : "r"(addr));
}

// ---------------------------------------------------------------------------
__global__ void init_k(const float* __restrict__ pc1, const float* __restrict__ pc2) {
    int idx = blockIdx.x * blockDim.x + threadIdx.x;
    if (idx >= BN) return;

    float x = pc1[3 * idx + 0], y = pc1[3 * idx + 1], z = pc1[3 * idx + 2];
    float sq = x * x + y * y + z * z;
    g_x1[idx] = x; g_y1[idx] = y; g_z1[idx] = z; g_sq1[idx] = sq; g_h1[idx] = -SF * sq;

    x = pc2[3 * idx + 0]; y = pc2[3 * idx + 1]; z = pc2[3 * idx + 2];
    sq = x * x + y * y + z * z;
    g_x2[idx] = x; g_y2[idx] = y; g_z2[idx] = z; g_sq2[idx] = sq; g_h2[idx] = -SF * sq;
}

// ---------------------------------------------------------------------------
// Half-step, 2 rows per lane. Lane owns rows rA = row0+lane, rB = rA+32;
// warp w owns j-chunk [w*128, w*128+128). Each LDS.128 of j-data feeds BOTH
// rows' f32x2 chains (halves smem traffic per element). Fixed-reference fast
// LSE (M0 = -h_old - log2N) + whole-warp online-max rescue on over/underflow.
// Merge across 16 warps in log domain; 64 rows written by threads 0..63.
// ---------------------------------------------------------------------------
__global__ void __launch_bounds__(UTPB, 2) upd_k(int dir) {
    const float* __restrict__ jx = dir ? g_x1 : g_x2;
    const float* __restrict__ jy = dir ? g_y1 : g_y2;
    const float* __restrict__ jz = dir ? g_z1 : g_z2;
    const float* __restrict__ jh = dir ? g_h1 : g_h2;
    const float* __restrict__ rx = dir ? g_x2 : g_x1;
    const float* __restrict__ ry = dir ? g_y2 : g_y1;
    const float* __restrict__ rz = dir ? g_z2 : g_z1;
    float*       __restrict__ rh = dir ? g_h2 : g_h1;

    __shared__ __align__(16) float sx[NP], sy[NP], sz[NP], shh[NP];   // 32 KB
    __shared__ float msh[UWARP][64], ssh[UWARP][64];                  // 8 KB

    const int tid  = threadIdx.x;
    const int lane = tid & 31;
    const int w    = tid >> 5;
    const int blk  = blockIdx.x;
    const int b    = blk >> 5;                 // 32 blocks per batch
    const int base = b * NP;
    const int row0 = base + ((blk & 31) << 6); // 64 rows per block
    const int o4   = (w << 5) + lane;          // float4 idx of warp's chunk elt

    // Per-warp staging of own 128-j chunk (1 float4 per lane per array)
    ((float4*)sx)[o4] = __ldg((const float4*)(jx + base) + o4);
    ((float4*)sy)[o4] = __ldg((const float4*)(jy + base) + o4);
    ((float4*)sz)[o4] = __ldg((const float4*)(jz + base) + o4);
    ((float4*)shh)[o4] = __ldg((const float4*)(jh + base) + o4);

    // Row-pair constants
    const int rA = row0 + lane, rB = rA + 32;
    float pxA = TWOSF * __ldg(rx + rA), pxB = TWOSF * __ldg(rx + rB);
    float pyA = TWOSF * __ldg(ry + rA), pyB = TWOSF * __ldg(ry + rB);
    float pzA = TWOSF * __ldg(rz + rA), pzB = TWOSF * __ldg(rz + rB);
    float hwA = __ldg(rh + rA) + LOG2NF;       // -M0 for row A
    float hwB = __ldg(rh + rB) + LOG2NF;
    __syncwarp();

    const float* qx = sx  + w * UJCH;
    const float* qy = sy  + w * UJCH;
    const float* qz = sz  + w * UJCH;
    const float* qh = shh + w * UJCH;

    ULL pxA2 = pack2(pxA, pxA), pyA2 = pack2(pyA, pyA), pzA2 = pack2(pzA, pzA);
    ULL pxB2 = pack2(pxB, pxB), pyB2 = pack2(pyB, pyB), pzB2 = pack2(pzB, pzB);
    ULL hwA2 = pack2(hwA, hwA), hwB2 = pack2(hwB, hwB);

    float sA0 = 0.f, sA1 = 0.f, sB0 = 0.f, sB1 = 0.f;

    #pragma unroll 2
    for (int j = 0; j < UJCH; j += 4) {
        ULL x01, x23, y01, y23, z01, z23, h01, h23;
        lds4(qx + j, x01, x23);
        lds4(qy + j, y01, y23);
        lds4(qz + j, z01, z23);
        lds4(qh + j, h01, h23);

        ULL AA01 = fma2(pxA2, x01, fma2(pyA2, y01, fma2(pzA2, z01, add2(h01, hwA2))));
        ULL AA23 = fma2(pxA2, x23, fma2(pyA2, y23, fma2(pzA2, z23, add2(h23, hwA2))));
        ULL AB01 = fma2(pxB2, x01, fma2(pyB2, y01, fma2(pzB2, z01, add2(h01, hwB2))));
        ULL AB23 = fma2(pxB2, x23, fma2(pyB2, y23, fma2(pzB2, z23, add2(h23, hwB2))));

        float a0, a1, a2, a3;
        unpack2(AA01, a0, a1);
        unpack2(AA23, a2, a3);
        sA0 += ex2f(a0);
        sA1 += ex2f(a1);
        sA0 += ex2f(a2);
        sA1 += ex2f(a3);
        unpack2(AB01, a0, a1);
        unpack2(AB23, a2, a3);
        sB0 += ex2f(a0);
        sB1 += ex2f(a1);
        sB0 += ex2f(a2);
        sB1 += ex2f(a3);
    }

    float SA = sA0 + sA1, SB = sB0 + sB1;
    float mA = -hwA, sAo = SA, mB = -hwB, sBo = SB;

    // Rescue: any lane over/underflowed in either row -> exact online-max redo
    bool ok = (SA > 0.0f) && (SA <= 3.3e38f) && (SB > 0.0f) && (SB <= 3.3e38f);
    if (__ballot_sync(0xffffffffu, !ok)) {
        float ma = -1e30f, sa = 0.f, mb = -1e30f, sb = 0.f;
        for (int j = 0; j < UJCH; j++) {
            float xx = qx[j], yy = qy[j], zz = qz[j], hh = qh[j];
            float Aa = fmaf(pxA, xx, fmaf(pyA, yy, fmaf(pzA, zz, hh)));
            float Ab = fmaf(pxB, xx, fmaf(pyB, yy, fmaf(pzB, zz, hh)));
            float na = fmaxf(Aa, ma), nb = fmaxf(Ab, mb);
            sa = sa * ex2f(ma - na) + ex2f(Aa - na);
            sb = sb * ex2f(mb - nb) + ex2f(Ab - nb);
            ma = na; mb = nb;
        }
        mA = ma; sAo = sa; mB = mb; sBo = sb;
    }

    msh[w][lane]      = mA;
    ssh[w][lane]      = sAo;
    msh[w][lane + 32] = mB;
    ssh[w][lane + 32] = sBo;
    __syncthreads();

    if (tid < 64) {
        float M = msh[0][tid];
        #pragma unroll
        for (int k = 1; k < UWARP; k++) M = fmaxf(M, msh[k][tid]);
        float S = 0.f;
        #pragma unroll
        for (int k = 0; k < UWARP; k++) S += ssh[k][tid] * ex2f(msh[k][tid] - M);
        rh[row0 + tid] = -LOG2NF - M - lg2f(S);
    }
}

// ---------------------------------------------------------------------------
// dist_i = N * sum_j exp2(h1_i + A_j) * C_ij ; C = sq1 + sq2 - (A - h_j)*eps*ln2
// Runs once; 8-warp j-split, per-warp SoA staging.
// ---------------------------------------------------------------------------
__global__ void __launch_bounds__(DTPB, 4) dist_k() {
    __shared__ __align__(16) float sx[NP], sy[NP], sz[NP], shh[NP], ssq[NP];
    __shared__ float ssh[DWARP][32];

    const int tid  = threadIdx.x;
    const int lane = tid & 31;
    const int w    = tid >> 5;
    const int blk  = blockIdx.x;
    const int b    = blk >> 6;
    const int base = b * NP;
    const int gi   = base + ((blk & 63) << 5) + lane;

    #pragma unroll
    for (int k = 0; k < 2; k++) {
        int o4 = (w * DJCH >> 2) + lane + 32 * k;
        ((float4*)sx)[o4]  = __ldg((const float4*)(g_x2 + base) + o4);
        ((float4*)sy)[o4]  = __ldg((const float4*)(g_y2 + base) + o4);
        ((float4*)sz)[o4]  = __ldg((const float4*)(g_z2 + base) + o4);
        ((float4*)shh)[o4] = __ldg((const float4*)(g_h2 + base) + o4);
        ((float4*)ssq)[o4] = __ldg((const float4*)(g_sq2 + base) + o4);
    }

    float px = TWOSF * __ldg(g_x1 + gi);
    float py = TWOSF * __ldg(g_y1 + gi);
    float pz = TWOSF * __ldg(g_z1 + gi);
    float sq1 = __ldg(g_sq1 + gi);
    float tf  = __ldg(g_h1 + gi);
    __syncwarp();

    const float* qx = sx  + w * DJCH;
    const float* qy = sy  + w * DJCH;
    const float* qz = sz  + w * DJCH;
    const float* qh = shh + w * DJCH;
    const float* qs = ssq + w * DJCH;

    float a0 = 0.f, a1 = 0.f, a2 = 0.f, a3 = 0.f;
    #pragma unroll 1
    for (int j = 0; j < DJCH; j += 4) {
        #pragma unroll
        for (int k = 0; k < 4; k++) {
            float hj = qh[j + k];
            float A  = fmaf(px, qx[j + k], fmaf(py, qy[j + k], fmaf(pz, qz[j + k], hj)));
            float e  = ex2f(tf + A);
            float C  = sq1 + qs[j + k] - (A - hj) * EPSLN2;
            float pc = e * C;
            if      (k == 0) a0 += pc;
            else if (k == 1) a1 += pc;
            else if (k == 2) a2 += pc;
            else             a3 += pc;
        }
    }
    ssh[w][lane] = (a0 + a1) + (a2 + a3);
    __syncthreads();

    if (w == 0) {
        float S = ssh[0][lane];
        #pragma unroll
        for (int k = 1; k < DWARP; k++) S += ssh[k][lane];
        float v = sqrtf((float)NP * S + 1e-12f);
        #pragma unroll
        for (int o = 16; o; o >>= 1) v += __shfl_xor_sync(0xffffffffu, v, o);
        if (lane == 0) g_part[blk] = v;
    }
}

// ---------------------------------------------------------------------------
__global__ void finish_k(float* __restrict__ out) {
    __shared__ float sh[BN / 32];
    int t = threadIdx.x;
    sh[t] = g_part[t];
    __syncthreads();
    for (int s = (BN / 32) / 2; s > 0; s >>= 1) {
        if (t < s) sh[t] += sh[t + s];
        __syncthreads();
    }
    if (t == 0) out[0] = sh[0] * (1.0f / (float)BN);
}

// ---------------------------------------------------------------------------
extern "C" void kernel_launch(void* const* d_in, const int* in_sizes, int n_in,
                              void* d_out, int out_size) {
    const float* pc1 = (const float*)d_in[0];
    const float* pc2 = (const float*)d_in[1];
    float* out = (float*)d_out;

    init_k<<<(BN + 255) / 256, 256>>>(pc1, pc2);

    for (int p = 0; p < PHASES; p++)
        upd_k<<<UGRID, UTPB>>>(p & 1);

    dist_k<<<BN / 32, DTPB>>>();
    finish_k<<<1, BN / 32>>>(out);

    (void)in_sizes; (void)n_in; (void)out_size;
}